// round 15
// baseline (speedup 1.0000x reference)
#include <cuda_runtime.h>

#define WW 4096
#define HH 4096
#define ROWS 32            // output rows per warp
#define OUTW 64            // output columns per strip (aligned, no masked lanes)
#define NSTRIPS 64
#define WARPS 4
#define NTHREADS 128
#define GRIDY 32           // HH / (ROWS * WARPS)
#define NBLOCKS (NSTRIPS * GRIDY)

__device__ double g_sum_d2 = 0.0;
__device__ double g_sum_G  = 0.0;
__device__ double g_cnt    = 0.0;
__device__ unsigned int g_done = 0u;

// L2-only aligned vector load (LDG.E.64.CG).
__device__ __forceinline__ float2 ldcg2(const float* p) {
    float2 v;
    asm volatile("ld.global.cg.v2.f32 {%0,%1}, [%2];"
                 : "=f"(v.x), "=f"(v.y) : "l"(p));
    return v;
}
// Predicated variant: lanes with pr==0 skip the access (no branch, no BSSY).
__device__ __forceinline__ float2 ldcg2_pred(const float* p, unsigned int pr) {
    float2 v;
    asm volatile("{\n\t"
                 ".reg .pred q;\n\t"
                 "setp.ne.u32 q, %3, 0;\n\t"
                 "mov.f32 %0, 0f00000000;\n\t"
                 "mov.f32 %1, 0f00000000;\n\t"
                 "@q ld.global.cg.v2.f32 {%0,%1}, [%2];\n\t"
                 "}" : "=f"(v.x), "=f"(v.y) : "l"(p), "r"(pr));
    return v;
}

struct DT { float2 d, t, dh; };   // dh: halo diff, valid in lanes 0/31 only

// Horizontal combined taps on 2 columns: A = [1,4,6,4,1], B = [-1,-2,0,2,1].
// MODE: 0 interior strip, 1 left image edge, 2 right image edge.
template <int MODE>
__device__ __forceinline__ void hpass2(float2 d, float2 dh, bool l0, bool l31,
                                       float2& A, float2& B) {
    float wm2 = __shfl_up_sync(0xffffffffu,   d.x, 1);
    float wm1 = __shfl_up_sync(0xffffffffu,   d.y, 1);
    float wp2 = __shfl_down_sync(0xffffffffu, d.x, 1);
    float wp3 = __shfl_down_sync(0xffffffffu, d.y, 1);
    if (MODE == 1) {                    // lane0: reflect-101 (d[-1]=d[1], d[-2]=d[2])
        float nm1 = l0 ? d.y : wm1;
        float nm2 = l0 ? wp2 : wm2;
        wm1 = nm1; wm2 = nm2;
        wp2 = l31 ? dh.x : wp2;
        wp3 = l31 ? dh.y : wp3;
    } else if (MODE == 2) {             // lane31: reflect (d[64]=d[62], d[65]=d[61])
        wm2 = l0 ? dh.x : wm2;
        wm1 = l0 ? dh.y : wm1;
        float np2 = l31 ? d.x : wp2;
        float np3 = l31 ? wm1 : wp3;    // lane31's wm1 is unpatched col 61
        wp2 = np2; wp3 = np3;
    } else {
        wm2 = l0 ? dh.x : wm2;
        wm1 = l0 ? dh.y : wm1;
        wp2 = l31 ? dh.x : wp2;
        wp3 = l31 ? dh.y : wp3;
    }
    float w0 = d.x, w1 = d.y;
    A.x = fmaf(6.f, w0, fmaf(4.f, wm1 + w1, wm2 + wp2));
    B.x = fmaf(2.f, w1 - wm1, wp2 - wm2);
    A.y = fmaf(6.f, w1, fmaf(4.f, w0 + wp2, wm1 + wp3));
    B.y = fmaf(2.f, wp2 - w0, wp3 - wm1);
}

__device__ __forceinline__ void mse2(float2 d, float2 t,
                                     float& accD2, float& accC) {
    if (t.x > 0.f) { accD2 = fmaf(d.x, d.x, accD2); accC += 1.f; }
    if (t.y > 0.f) { accD2 = fmaf(d.y, d.y, accD2); accC += 1.f; }
}

// dx^2 - dy^2 = (dx+dy)*(dx-dy)
__device__ __forceinline__ float vcomp(float b0, float b1, float b2, float b3, float b4,
                                       float a0, float a1, float a3, float a4) {
    float dx = fmaf(6.f, b2, fmaf(4.f, b1 + b3, b0 + b4));
    float dy = fmaf(2.f, a3 - a1, a4 - a0);
    return (dx + dy) * (dx - dy);
}

template <int MODE>
__device__ __forceinline__ void run_band(
    const float* __restrict__ predc, const float* __restrict__ targc,  // + colbase
    int y0, int lo, int hoff, unsigned int prH, bool l0, bool l31,
    float& accD2, float& accC, float& accG)
{
    float2 A0, A1, A2, A3, B0, B1, B2, B3;

    auto load = [&](const float* __restrict__ pp,
                    const float* __restrict__ tp) -> DT {
        DT r;
        float2 p  = ldcg2(pp + lo);
        float2 t  = ldcg2(tp + lo);
        float2 ph = ldcg2_pred(pp + hoff, prH);
        float2 th = ldcg2_pred(tp + hoff, prH);
        r.t = t;
        r.d  = make_float2(p.x - t.x, p.y - t.y);
        r.dh = make_float2(ph.x - th.x, ph.y - th.y);
        return r;
    };

    auto proc = [&](const DT& q, bool do_mse) {
        if (do_mse) mse2(q.d, q.t, accD2, accC);
        float2 A4, B4; hpass2<MODE>(q.d, q.dh, l0, l31, A4, B4);
        accG += vcomp(B0.x, B1.x, B2.x, B3.x, B4.x, A0.x, A1.x, A3.x, A4.x);
        accG += vcomp(B0.y, B1.y, B2.y, B3.y, B4.y, A0.y, A1.y, A3.y, A4.y);
        A0 = A1; A1 = A2; A2 = A3; A3 = A4;
        B0 = B1; B1 = B2; B2 = B3; B3 = B4;
    };

    // ---- Prologue: rows y0-2 .. y0+1 (top reflect; MSE on last two) ----
    {
        int rm2 = y0 - 2; if (rm2 < 0) rm2 = -rm2;
        int rm1 = y0 - 1; if (rm1 < 0) rm1 = -rm1;
        { DT q = load(predc + rm2 * WW, targc + rm2 * WW); float2 a,b;
          hpass2<MODE>(q.d, q.dh, l0, l31, a, b); A0 = a; B0 = b; }
        { DT q = load(predc + rm1 * WW, targc + rm1 * WW); float2 a,b;
          hpass2<MODE>(q.d, q.dh, l0, l31, a, b); A1 = a; B1 = b; }
        { DT q = load(predc + y0 * WW, targc + y0 * WW);
          mse2(q.d, q.t, accD2, accC); float2 a,b;
          hpass2<MODE>(q.d, q.dh, l0, l31, a, b); A2 = a; B2 = b; }
        { DT q = load(predc + (y0 + 1) * WW, targc + (y0 + 1) * WW);
          mse2(q.d, q.t, accD2, accC); float2 a,b;
          hpass2<MODE>(q.d, q.dh, l0, l31, a, b); A3 = a; B3 = b; }
    }

    // ---- Main: rows y0+2 .. y0+29, 7 chunks x 4 rows, loads front-batched ----
    const float* pp = predc + (y0 + 2) * WW;
    const float* tp = targc + (y0 + 2) * WW;
    #pragma unroll 1
    for (int c = 0; c < 7; c++) {
        DT q0 = load(pp,          tp);
        DT q1 = load(pp + WW,     tp + WW);
        DT q2 = load(pp + 2 * WW, tp + 2 * WW);
        DT q3 = load(pp + 3 * WW, tp + 3 * WW);
        pp += 4 * WW; tp += 4 * WW;
        proc(q0, true); proc(q1, true); proc(q2, true); proc(q3, true);
    }

    // ---- Rows y0+30, y0+31 (core, MSE; always interior rows) ----
    {
        DT q0 = load(pp,      tp);
        DT q1 = load(pp + WW, tp + WW);
        proc(q0, true); proc(q1, true);
    }

    // ---- Rows y0+32, y0+33 (bottom reflect; halo only) ----
    {
        int ra = y0 + ROWS;     if (ra >= HH) ra = 2 * HH - 2 - ra;
        int rb = y0 + ROWS + 1; if (rb >= HH) rb = 2 * HH - 2 - rb;
        DT q0 = load(predc + ra * WW, targc + ra * WW);
        DT q1 = load(predc + rb * WW, targc + rb * WW);
        proc(q0, false); proc(q1, false);
    }
}

__global__ __launch_bounds__(NTHREADS, 6)
void loss_kernel(const float* __restrict__ pred, const float* __restrict__ target,
                 float* __restrict__ out) {
    __shared__ float s_d2[WARPS], s_g[WARPS], s_c[WARPS];
    __shared__ bool  s_last;

    const int lane = threadIdx.x & 31;
    const int wid  = threadIdx.x >> 5;
    const int s    = blockIdx.x;
    const int y0   = (blockIdx.y * WARPS + wid) * ROWS;

    const int colbase = s * OUTW;                 // 256B aligned
    const int lo      = lane * 2;                 // aligned LDG.64, 2 wf each
    const int hoff    = (lane == 31) ? OUTW : -2; // halo window per edge lane
    const bool l0  = (lane == 0);
    const bool l31 = (lane == 31);

    const float* predc = pred + colbase;
    const float* targc = target + colbase;

    float accD2 = 0.f, accC = 0.f, accG = 0.f;

    if (s == 0) {
        unsigned int prH = l31 ? 1u : 0u;
        run_band<1>(predc, targc, y0, lo, hoff, prH, l0, l31, accD2, accC, accG);
    } else if (s == NSTRIPS - 1) {
        unsigned int prH = l0 ? 1u : 0u;
        run_band<2>(predc, targc, y0, lo, hoff, prH, l0, l31, accD2, accC, accG);
    } else {
        unsigned int prH = (l0 || l31) ? 1u : 0u;
        run_band<0>(predc, targc, y0, lo, hoff, prH, l0, l31, accD2, accC, accG);
    }

    // ---- Reduce (all lanes fully valid; no masking needed) ----
    #pragma unroll
    for (int off = 16; off > 0; off >>= 1) {
        accD2 += __shfl_down_sync(0xffffffffu, accD2, off);
        accG  += __shfl_down_sync(0xffffffffu, accG,  off);
        accC  += __shfl_down_sync(0xffffffffu, accC,  off);
    }
    if (lane == 0) { s_d2[wid] = accD2; s_g[wid] = accG; s_c[wid] = accC; }
    __syncthreads();
    if (threadIdx.x == 0) {
        float t2 = 0.f, tg = 0.f, tc = 0.f;
        #pragma unroll
        for (int i = 0; i < WARPS; i++) { t2 += s_d2[i]; tg += s_g[i]; tc += s_c[i]; }
        atomicAdd(&g_sum_d2, (double)t2);
        atomicAdd(&g_sum_G,  (double)tg);
        atomicAdd(&g_cnt,    (double)tc);
        __threadfence();
        unsigned int done = atomicAdd(&g_done, 1u);
        s_last = (done == NBLOCKS - 1);
    }
    __syncthreads();

    if (s_last && threadIdx.x == 0) {
        double sd2 = *(volatile double*)&g_sum_d2;
        double sg  = *(volatile double*)&g_sum_G;
        double n   = *(volatile double*)&g_cnt;
        if (n < 1.0) n = 1.0;
        double mae = sd2 / n;
        double G = sg / (256.0 * (double)WW * (double)HH);   // taps were 16x true
        out[0] = (float)(0.2 * G + 0.8 * mae);
        *(volatile double*)&g_sum_d2 = 0.0;
        *(volatile double*)&g_sum_G  = 0.0;
        *(volatile double*)&g_cnt    = 0.0;
        *(volatile unsigned int*)&g_done = 0u;
    }
}

extern "C" void kernel_launch(void* const* d_in, const int* in_sizes, int n_in,
                              void* d_out, int out_size) {
    const float* pred   = (const float*)d_in[0];
    const float* target = (const float*)d_in[1];
    float* out = (float*)d_out;

    dim3 grid(NSTRIPS, GRIDY);
    loss_kernel<<<grid, NTHREADS>>>(pred, target, out);
}

// round 16
// speedup vs baseline: 1.1107x; 1.1107x over previous
#include <cuda_runtime.h>

#define WW 4096
#define HH 4096
#define ROWS 32            // output rows per warp
#define OUTW 60            // output columns per strip (warp loads 64 via float2)
#define NSTRIPS 69         // 69*60 = 4140 >= 4096
#define WARPS 4
#define NTHREADS 128
#define GRIDY 32           // HH / (ROWS * WARPS)
#define NBLOCKS (NSTRIPS * GRIDY)

__device__ double g_sum_d2 = 0.0;
__device__ double g_sum_G  = 0.0;
__device__ double g_cnt    = 0.0;
__device__ unsigned int g_done = 0u;

__device__ __forceinline__ int reflc(int i) {          // reflect-101, width WW
    if (i < 0) i = -i;
    if (i >= WW) i = 2 * WW - 2 - i;
    return i;
}

// L2-only loads (skip L1 allocate/fill — LDG.E.CG in SASS).
__device__ __forceinline__ float2 ldcg2(const float* p) {
    float2 v;
    asm volatile("ld.global.cg.v2.f32 {%0,%1}, [%2];"
                 : "=f"(v.x), "=f"(v.y) : "l"(p));
    return v;
}
__device__ __forceinline__ float ldcg1(const float* p) {
    float v;
    asm volatile("ld.global.cg.f32 %0, [%1];" : "=f"(v) : "l"(p));
    return v;
}

struct DT { float2 d, t; };

// Horizontal combined taps on 2 columns: A = [1,4,6,4,1], B = [-1,-2,0,2,1]
__device__ __forceinline__ void hpass2(float2 d, float2& A, float2& B) {
    float wm2 = __shfl_up_sync(0xffffffffu,   d.x, 1);
    float wm1 = __shfl_up_sync(0xffffffffu,   d.y, 1);
    float wp2 = __shfl_down_sync(0xffffffffu, d.x, 1);
    float wp3 = __shfl_down_sync(0xffffffffu, d.y, 1);
    float w0 = d.x, w1 = d.y;
    A.x = fmaf(6.f, w0, fmaf(4.f, wm1 + w1, wm2 + wp2));
    B.x = fmaf(2.f, w1 - wm1, wp2 - wm2);
    A.y = fmaf(6.f, w1, fmaf(4.f, w0 + wp2, wm1 + wp3));
    B.y = fmaf(2.f, wp2 - w0, wp3 - wm1);
}

// Unmasked MSE terms (predicated FFMA/FADD); halo lanes zeroed at the end.
__device__ __forceinline__ void mse2(float2 d, float2 t,
                                     float& accD2, float& accC) {
    if (t.x > 0.f) { accD2 = fmaf(d.x, d.x, accD2); accC += 1.f; }
    if (t.y > 0.f) { accD2 = fmaf(d.y, d.y, accD2); accC += 1.f; }
}

// dx^2 - dy^2 = (dx+dy)*(dx-dy), unmasked.
__device__ __forceinline__ float vcomp(float b0, float b1, float b2, float b3, float b4,
                                       float a0, float a1, float a3, float a4) {
    float dx = fmaf(6.f, b2, fmaf(4.f, b1 + b3, b0 + b4));
    float dy = fmaf(2.f, a3 - a1, a4 - a0);
    return (dx + dy) * (dx - dy);
}

// Whole band, specialized on EDGE. Interior warps: software-pipelined chunks —
// each iteration FIRST issues the next chunk's 8 LDG.64.CG, THEN computes the
// current chunk, so loads are always in flight during compute.
template <bool EDGE>
__device__ __forceinline__ void run_band(
    const float* __restrict__ pred, const float* __restrict__ target,
    int y0, int xb, int c0, int c1,
    float& accD2, float& accC, float& accG)
{
    float2 A0, A1, A2, A3, B0, B1, B2, B3;

    auto load = [&](const float* __restrict__ pp,
                    const float* __restrict__ tp) -> DT {
        DT r;
        if (EDGE) {
            float t0 = ldcg1(tp + c0), p0 = ldcg1(pp + c0);
            float t1 = ldcg1(tp + c1), p1 = ldcg1(pp + c1);
            r.t = make_float2(t0, t1);
            r.d = make_float2(p0 - t0, p1 - t1);
        } else {
            float2 p = ldcg2(pp + xb);
            float2 t = ldcg2(tp + xb);
            r.t = t;
            r.d = make_float2(p.x - t.x, p.y - t.y);
        }
        return r;
    };

    auto proc = [&](const DT& q, bool do_mse) {
        if (do_mse) mse2(q.d, q.t, accD2, accC);
        float2 A4, B4; hpass2(q.d, A4, B4);
        accG += vcomp(B0.x, B1.x, B2.x, B3.x, B4.x, A0.x, A1.x, A3.x, A4.x);
        accG += vcomp(B0.y, B1.y, B2.y, B3.y, B4.y, A0.y, A1.y, A3.y, A4.y);
        A0 = A1; A1 = A2; A2 = A3; A3 = A4;
        B0 = B1; B1 = B2; B2 = B3; B3 = B4;
    };

    // ---- Prologue: rows y0-2 .. y0+1 (top reflect; MSE on last two) ----
    {
        int rm2 = y0 - 2; if (rm2 < 0) rm2 = -rm2;
        int rm1 = y0 - 1; if (rm1 < 0) rm1 = -rm1;
        { DT q = load(pred + rm2 * WW, target + rm2 * WW); hpass2(q.d, A0, B0); }
        { DT q = load(pred + rm1 * WW, target + rm1 * WW); hpass2(q.d, A1, B1); }
        { DT q = load(pred + y0 * WW, target + y0 * WW);
          mse2(q.d, q.t, accD2, accC); hpass2(q.d, A2, B2); }
        { DT q = load(pred + (y0 + 1) * WW, target + (y0 + 1) * WW);
          mse2(q.d, q.t, accD2, accC); hpass2(q.d, A3, B3); }
    }

    // ---- Pipelined main: 7 chunks x 4 rows (y0+2 .. y0+29).
    //      Chunk 0 preloaded; loop issues chunk c+1's loads before computing c.
    const float* pp = pred   + (y0 + 2) * WW;
    const float* tp = target + (y0 + 2) * WW;
    DT q0 = load(pp,          tp);
    DT q1 = load(pp + WW,     tp + WW);
    DT q2 = load(pp + 2 * WW, tp + 2 * WW);
    DT q3 = load(pp + 3 * WW, tp + 3 * WW);
    pp += 4 * WW; tp += 4 * WW;

    #pragma unroll 2
    for (int c = 0; c < 6; c++) {
        DT n0 = load(pp,          tp);
        DT n1 = load(pp + WW,     tp + WW);
        DT n2 = load(pp + 2 * WW, tp + 2 * WW);
        DT n3 = load(pp + 3 * WW, tp + 3 * WW);
        pp += 4 * WW; tp += 4 * WW;
        proc(q0, true); proc(q1, true); proc(q2, true); proc(q3, true);
        q0 = n0; q1 = n1; q2 = n2; q3 = n3;
    }

    // ---- Final special chunk: rows y0+30, y0+31 (core) + 2 reflected rows.
    //      Issue its loads before computing the 7th main chunk.
    {
        int ra = y0 + ROWS;     if (ra >= HH) ra = 2 * HH - 2 - ra;
        int rb = y0 + ROWS + 1; if (rb >= HH) rb = 2 * HH - 2 - rb;
        DT n0 = load(pp,      tp);
        DT n1 = load(pp + WW, tp + WW);
        DT n2 = load(pred + ra * WW, target + ra * WW);
        DT n3 = load(pred + rb * WW, target + rb * WW);
        proc(q0, true); proc(q1, true); proc(q2, true); proc(q3, true);
        proc(n0, true); proc(n1, true);
        proc(n2, false); proc(n3, false);
    }
}

__global__ __launch_bounds__(NTHREADS, 6)
void loss_kernel(const float* __restrict__ pred, const float* __restrict__ target,
                 float* __restrict__ out) {
    __shared__ float s_d2[WARPS], s_g[WARPS], s_c[WARPS];
    __shared__ bool  s_last;

    const int lane = threadIdx.x & 31;
    const int wid  = threadIdx.x >> 5;
    const int s    = blockIdx.x;
    const int y0   = (blockIdx.y * WARPS + wid) * ROWS;

    const int xb   = s * OUTW - 2 + lane * 2;        // 8B-aligned when interior
    const bool inx = (xb >= 0) && (xb + 1 < WW);
    const int c0 = reflc(xb), c1 = reflc(xb + 1);

    // Lane validity (xb even; window bounds make x/x+1 identical — see R10):
    const int outlo = s * OUTW;
    const int outhi = s * OUTW + OUTW - 1;
    const float actf =
        (xb >= outlo && xb <= outhi && (unsigned)xb < WW) ? 1.f : 0.f;

    float accD2 = 0.f, accC = 0.f, accG = 0.f;

    if (__any_sync(0xffffffffu, !inx))
        run_band<true >(pred, target, y0, xb, c0, c1, accD2, accC, accG);
    else
        run_band<false>(pred, target, y0, xb, c0, c1, accD2, accC, accG);

    // ---- Apply lane mask once, then reduce ----
    accD2 *= actf; accG *= actf; accC *= actf;

    #pragma unroll
    for (int off = 16; off > 0; off >>= 1) {
        accD2 += __shfl_down_sync(0xffffffffu, accD2, off);
        accG  += __shfl_down_sync(0xffffffffu, accG,  off);
        accC  += __shfl_down_sync(0xffffffffu, accC,  off);
    }
    if (lane == 0) { s_d2[wid] = accD2; s_g[wid] = accG; s_c[wid] = accC; }
    __syncthreads();
    if (threadIdx.x == 0) {
        float t2 = 0.f, tg = 0.f, tc = 0.f;
        #pragma unroll
        for (int i = 0; i < WARPS; i++) { t2 += s_d2[i]; tg += s_g[i]; tc += s_c[i]; }
        atomicAdd(&g_sum_d2, (double)t2);
        atomicAdd(&g_sum_G,  (double)tg);
        atomicAdd(&g_cnt,    (double)tc);
        __threadfence();
        unsigned int done = atomicAdd(&g_done, 1u);
        s_last = (done == NBLOCKS - 1);
    }
    __syncthreads();

    if (s_last && threadIdx.x == 0) {
        double sd2 = *(volatile double*)&g_sum_d2;
        double sg  = *(volatile double*)&g_sum_G;
        double n   = *(volatile double*)&g_cnt;
        if (n < 1.0) n = 1.0;
        double mae = sd2 / n;
        double G = sg / (256.0 * (double)WW * (double)HH);   // taps were 16x true
        out[0] = (float)(0.2 * G + 0.8 * mae);
        *(volatile double*)&g_sum_d2 = 0.0;
        *(volatile double*)&g_sum_G  = 0.0;
        *(volatile double*)&g_cnt    = 0.0;
        *(volatile unsigned int*)&g_done = 0u;
    }
}

extern "C" void kernel_launch(void* const* d_in, const int* in_sizes, int n_in,
                              void* d_out, int out_size) {
    const float* pred   = (const float*)d_in[0];
    const float* target = (const float*)d_in[1];
    float* out = (float*)d_out;

    dim3 grid(NSTRIPS, GRIDY);
    loss_kernel<<<grid, NTHREADS>>>(pred, target, out);
}